// round 1
// baseline (speedup 1.0000x reference)
#include <cuda_runtime.h>

#define NN 50000
#define EE 800000
#define FIN 128
#define HH 4
#define FO 64
#define NOUT 256   // HH*FO

// ---- static scratch (no allocation allowed) ----
__device__ float g_ft[NN * NOUT];     // projected features [N,256]
__device__ float g_el2[NN * HH];
__device__ float g_er2[NN * HH];
__device__ float g_wc[HH * FIN];      // attn_l*attn_r - 2*attn_l1*attn_r1
__device__ int   g_counts[NN];
__device__ int   g_offsets[NN + 1];
__device__ int   g_cursor[NN];
__device__ int   g_csr_src[EE];
__device__ int   g_chunksum[64];

// ---------------- prep: wc + zero counts ----------------
__global__ void k_prep(const float* __restrict__ al, const float* __restrict__ ar,
                       const float* __restrict__ al1, const float* __restrict__ ar1) {
    int i = blockIdx.x * blockDim.x + threadIdx.x;
    if (i < HH * FIN) g_wc[i] = al[i] * ar[i] - 2.0f * al1[i] * ar1[i];
    if (i < NN) g_counts[i] = 0;
}

// ---------------- per-node el2/er2 (warp per node) ----------------
__global__ void k_node(const float* __restrict__ feat,
                       const float* __restrict__ al1, const float* __restrict__ ar1) {
    int warp = (blockIdx.x * blockDim.x + threadIdx.x) >> 5;
    int lane = threadIdx.x & 31;
    if (warp >= NN) return;
    float4 f = *(const float4*)(feat + warp * FIN + lane * 4);
    float q0 = f.x * f.x, q1 = f.y * f.y, q2 = f.z * f.z, q3 = f.w * f.w;
    float pl[4], pr[4];
#pragma unroll
    for (int h = 0; h < 4; h++) {
        float4 a = *(const float4*)(al1 + h * FIN + lane * 4);
        float4 b = *(const float4*)(ar1 + h * FIN + lane * 4);
        pl[h] = q0 * a.x * a.x + q1 * a.y * a.y + q2 * a.z * a.z + q3 * a.w * a.w;
        pr[h] = q0 * b.x * b.x + q1 * b.y * b.y + q2 * b.z * b.z + q3 * b.w * b.w;
    }
#pragma unroll
    for (int off = 16; off; off >>= 1) {
#pragma unroll
        for (int h = 0; h < 4; h++) {
            pl[h] += __shfl_xor_sync(0xffffffffu, pl[h], off);
            pr[h] += __shfl_xor_sync(0xffffffffu, pr[h], off);
        }
    }
    if (lane == 0) {
        float4 l4 = make_float4(pl[0], pl[1], pl[2], pl[3]);
        float4 r4 = make_float4(pr[0], pr[1], pr[2], pr[3]);
        *(float4*)(g_el2 + warp * 4) = l4;
        *(float4*)(g_er2 + warp * 4) = r4;
    }
}

// ---------------- SGEMM: ft = feat @ fc_w^T  (M=50000, N=256, K=128) ----------------
__global__ void __launch_bounds__(256, 2)
k_gemm(const float* __restrict__ A, const float* __restrict__ W) {
    __shared__ float As[8][128];
    __shared__ float Bs[8][128];
    const int mBase = blockIdx.y * 128;
    const int nBase = blockIdx.x * 128;
    const int tid = threadIdx.x;
    const int tr = tid / 16, tc = tid % 16;
    const int lr = tid >> 1;
    const int lc = (tid & 1) * 4;

    float acc[8][8];
#pragma unroll
    for (int i = 0; i < 8; i++)
#pragma unroll
        for (int j = 0; j < 8; j++) acc[i][j] = 0.0f;

    for (int kk = 0; kk < FIN; kk += 8) {
        int arow = mBase + lr;
        float4 av = make_float4(0.f, 0.f, 0.f, 0.f);
        if (arow < NN) av = *(const float4*)(A + arow * FIN + kk + lc);
        As[lc + 0][lr] = av.x; As[lc + 1][lr] = av.y;
        As[lc + 2][lr] = av.z; As[lc + 3][lr] = av.w;

        float4 bv = *(const float4*)(W + (nBase + lr) * FIN + kk + lc);
        Bs[lc + 0][lr] = bv.x; Bs[lc + 1][lr] = bv.y;
        Bs[lc + 2][lr] = bv.z; Bs[lc + 3][lr] = bv.w;
        __syncthreads();

#pragma unroll
        for (int k = 0; k < 8; k++) {
            float am[8], bn[8];
            *(float4*)(am)     = *(const float4*)(&As[k][tr * 8]);
            *(float4*)(am + 4) = *(const float4*)(&As[k][tr * 8 + 4]);
            *(float4*)(bn)     = *(const float4*)(&Bs[k][tc * 8]);
            *(float4*)(bn + 4) = *(const float4*)(&Bs[k][tc * 8 + 4]);
#pragma unroll
            for (int i = 0; i < 8; i++)
#pragma unroll
                for (int j = 0; j < 8; j++) acc[i][j] += am[i] * bn[j];
        }
        __syncthreads();
    }

#pragma unroll
    for (int i = 0; i < 8; i++) {
        int row = mBase + tr * 8 + i;
        if (row < NN) {
            float4 o0 = make_float4(acc[i][0], acc[i][1], acc[i][2], acc[i][3]);
            float4 o1 = make_float4(acc[i][4], acc[i][5], acc[i][6], acc[i][7]);
            *(float4*)(g_ft + row * NOUT + nBase + tc * 8)     = o0;
            *(float4*)(g_ft + row * NOUT + nBase + tc * 8 + 4) = o1;
        }
    }
}

// ---------------- CSR build ----------------
__global__ void k_hist(const int* __restrict__ dst) {
    int e = blockIdx.x * blockDim.x + threadIdx.x;
    if (e < EE) atomicAdd(&g_counts[dst[e]], 1);
}

__global__ void k_scan1() {
    __shared__ int s[1024];
    int tid = threadIdx.x;
    int t = blockIdx.x * 1024 + tid;
    int v = (t < NN) ? g_counts[t] : 0;
    s[tid] = v;
    __syncthreads();
    for (int off = 1; off < 1024; off <<= 1) {
        int x = (tid >= off) ? s[tid - off] : 0;
        __syncthreads();
        s[tid] += x;
        __syncthreads();
    }
    if (t < NN) g_offsets[t + 1] = s[tid];
    if (tid == 1023) g_chunksum[blockIdx.x] = s[1023];
}

__global__ void k_scan2(int nch) {
    if (threadIdx.x == 0 && blockIdx.x == 0) {
        int run = 0;
        for (int i = 0; i < nch; i++) { int t = g_chunksum[i]; g_chunksum[i] = run; run += t; }
    }
}

__global__ void k_scan3() {
    int tid = threadIdx.x;
    int t = blockIdx.x * 1024 + tid;
    if (t < NN) {
        int inc = g_offsets[t + 1] + g_chunksum[blockIdx.x];
        g_offsets[t + 1] = inc;
        g_cursor[t] = inc - g_counts[t];   // exclusive start of node t
    }
    if (t == 0) g_offsets[0] = 0;
}

__global__ void k_scatter(const int* __restrict__ src, const int* __restrict__ dst) {
    int e = blockIdx.x * blockDim.x + threadIdx.x;
    if (e < EE) {
        int d = dst[e];
        int pos = atomicAdd(&g_cursor[d], 1);
        g_csr_src[pos] = src[e];
    }
}

// ---------------- fused edge-score + online-softmax + aggregation ----------------
// one warp per destination node
__global__ void __launch_bounds__(256)
k_agg(const float* __restrict__ feat, const float* __restrict__ bias,
      float* __restrict__ out) {
    int warp = (blockIdx.x * blockDim.x + threadIdx.x) >> 5;
    int lane = threadIdx.x & 31;
    if (warp >= NN) return;
    const int n = warp;
    const int start = g_offsets[n];
    const int end = g_offsets[n + 1];

    float4 bA = *(const float4*)(bias + lane * 4);
    float4 bB = *(const float4*)(bias + 128 + lane * 4);

    if (start == end) {  // no incoming edges: output = bias (matches reference)
        *(float4*)(out + n * NOUT + lane * 4) = bA;
        *(float4*)(out + n * NOUT + 128 + lane * 4) = bB;
        return;
    }

    float4 fd = *(const float4*)(feat + n * FIN + lane * 4);
    float4 c0 = *(const float4*)(g_wc + 0 * FIN + lane * 4);
    float4 c1 = *(const float4*)(g_wc + 1 * FIN + lane * 4);
    float4 c2 = *(const float4*)(g_wc + 2 * FIN + lane * 4);
    float4 c3 = *(const float4*)(g_wc + 3 * FIN + lane * 4);
    float4 er = *(const float4*)(g_er2 + n * 4);

    const bool hi = (lane & 16) != 0;
    float m0 = -3.0e38f, m1 = -3.0e38f, m2 = -3.0e38f, m3 = -3.0e38f;
    float s0 = 0.f, s1 = 0.f, s2 = 0.f, s3 = 0.f;
    float4 accA = make_float4(0.f, 0.f, 0.f, 0.f);
    float4 accB = make_float4(0.f, 0.f, 0.f, 0.f);

    for (int idx = start; idx < end; ++idx) {
        int src = g_csr_src[idx];
        float4 fs  = *(const float4*)(feat + src * FIN + lane * 4);
        float4 ftA = *(const float4*)(g_ft + src * NOUT + lane * 4);
        float4 ftB = *(const float4*)(g_ft + src * NOUT + 128 + lane * 4);
        float4 el  = *(const float4*)(g_el2 + src * 4);

        float t0 = fs.x * fd.x, t1 = fs.y * fd.y, t2 = fs.z * fd.z, t3 = fs.w * fd.w;
        float p0 = t0 * c0.x + t1 * c0.y + t2 * c0.z + t3 * c0.w;
        float p1 = t0 * c1.x + t1 * c1.y + t2 * c1.z + t3 * c1.w;
        float p2 = t0 * c2.x + t1 * c2.y + t2 * c2.z + t3 * c2.w;
        float p3 = t0 * c3.x + t1 * c3.y + t2 * c3.z + t3 * c3.w;
#pragma unroll
        for (int off = 16; off; off >>= 1) {
            p0 += __shfl_xor_sync(0xffffffffu, p0, off);
            p1 += __shfl_xor_sync(0xffffffffu, p1, off);
            p2 += __shfl_xor_sync(0xffffffffu, p2, off);
            p3 += __shfl_xor_sync(0xffffffffu, p3, off);
        }
        float e0 = p0 + el.x + er.x;
        float e1 = p1 + el.y + er.y;
        float e2 = p2 + el.z + er.z;
        float e3 = p3 + el.w + er.w;

        // online softmax per head; rescale-branch is warp-uniform
        float sc0 = 1.f, sc1 = 1.f, sc2 = 1.f, sc3 = 1.f;
        if (e0 > m0) { sc0 = __expf(m0 - e0); m0 = e0; }
        if (e1 > m1) { sc1 = __expf(m1 - e1); m1 = e1; }
        if (e2 > m2) { sc2 = __expf(m2 - e2); m2 = e2; }
        if (e3 > m3) { sc3 = __expf(m3 - e3); m3 = e3; }
        float w0 = __expf(e0 - m0);
        float w1 = __expf(e1 - m1);
        float w2 = __expf(e2 - m2);
        float w3 = __expf(e3 - m3);
        s0 = s0 * sc0 + w0;
        s1 = s1 * sc1 + w1;
        s2 = s2 * sc2 + w2;
        s3 = s3 * sc3 + w3;

        float sA = hi ? sc1 : sc0, wA = hi ? w1 : w0;
        float sB = hi ? sc3 : sc2, wB = hi ? w3 : w2;
        accA.x = accA.x * sA + wA * ftA.x;
        accA.y = accA.y * sA + wA * ftA.y;
        accA.z = accA.z * sA + wA * ftA.z;
        accA.w = accA.w * sA + wA * ftA.w;
        accB.x = accB.x * sB + wB * ftB.x;
        accB.y = accB.y * sB + wB * ftB.y;
        accB.z = accB.z * sB + wB * ftB.z;
        accB.w = accB.w * sB + wB * ftB.w;
    }

    float rA = 1.f / (hi ? s1 : s0);
    float rB = 1.f / (hi ? s3 : s2);
    float4 oA = make_float4(accA.x * rA + bA.x, accA.y * rA + bA.y,
                            accA.z * rA + bA.z, accA.w * rA + bA.w);
    float4 oB = make_float4(accB.x * rB + bB.x, accB.y * rB + bB.y,
                            accB.z * rB + bB.z, accB.w * rB + bB.w);
    *(float4*)(out + n * NOUT + lane * 4) = oA;
    *(float4*)(out + n * NOUT + 128 + lane * 4) = oB;
}

// ---------------- launch ----------------
extern "C" void kernel_launch(void* const* d_in, const int* in_sizes, int n_in,
                              void* d_out, int out_size) {
    const float* feat  = (const float*)d_in[0];
    const int*   src   = (const int*)d_in[1];
    const int*   dst   = (const int*)d_in[2];
    const float* fc_w  = (const float*)d_in[3];
    const float* al    = (const float*)d_in[4];
    const float* ar    = (const float*)d_in[5];
    const float* al1   = (const float*)d_in[6];
    const float* ar1   = (const float*)d_in[7];
    const float* bias  = (const float*)d_in[8];
    float* out = (float*)d_out;

    const int nch = (NN + 1023) / 1024;  // 49

    k_prep<<<(NN + 255) / 256, 256>>>(al, ar, al1, ar1);
    k_node<<<(NN * 32 + 255) / 256, 256>>>(feat, al1, ar1);
    k_gemm<<<dim3(2, (NN + 127) / 128), 256>>>(feat, fc_w);
    k_hist<<<(EE + 255) / 256, 256>>>(dst);
    k_scan1<<<nch, 1024>>>();
    k_scan2<<<1, 32>>>(nch);
    k_scan3<<<nch, 1024>>>();
    k_scatter<<<(EE + 255) / 256, 256>>>(src, dst);
    k_agg<<<(NN * 32 + 255) / 256, 256>>>(feat, bias, out);
}

// round 2
// speedup vs baseline: 1.2948x; 1.2948x over previous
#include <cuda_runtime.h>

#define NN 50000
#define EE 800000
#define FIN 128
#define HH 4
#define FO 64
#define NOUT 256   // HH*FO

// ---- static scratch (no allocation allowed) ----
__device__ float g_z[NN * HH * FIN];  // aggregated features in input space [N,4,128]
__device__ float g_el2[NN * HH];
__device__ float g_er2[NN * HH];
__device__ float g_wc[HH * FIN];      // attn_l*attn_r - 2*attn_l1*attn_r1
__device__ int   g_counts[NN];
__device__ int   g_offsets[NN + 1];
__device__ int   g_cursor[NN];
__device__ int   g_csr_src[EE];
__device__ int   g_chunksum[64];

// ---------------- prep: wc + zero counts ----------------
__global__ void k_prep(const float* __restrict__ al, const float* __restrict__ ar,
                       const float* __restrict__ al1, const float* __restrict__ ar1) {
    int i = blockIdx.x * blockDim.x + threadIdx.x;
    if (i < HH * FIN) g_wc[i] = al[i] * ar[i] - 2.0f * al1[i] * ar1[i];
    if (i < NN) g_counts[i] = 0;
}

// ---------------- per-node el2/er2 (warp per node) ----------------
__global__ void k_node(const float* __restrict__ feat,
                       const float* __restrict__ al1, const float* __restrict__ ar1) {
    int warp = (blockIdx.x * blockDim.x + threadIdx.x) >> 5;
    int lane = threadIdx.x & 31;
    if (warp >= NN) return;
    float4 f = *(const float4*)(feat + warp * FIN + lane * 4);
    float q0 = f.x * f.x, q1 = f.y * f.y, q2 = f.z * f.z, q3 = f.w * f.w;
    float pl[4], pr[4];
#pragma unroll
    for (int h = 0; h < 4; h++) {
        float4 a = *(const float4*)(al1 + h * FIN + lane * 4);
        float4 b = *(const float4*)(ar1 + h * FIN + lane * 4);
        pl[h] = q0 * a.x * a.x + q1 * a.y * a.y + q2 * a.z * a.z + q3 * a.w * a.w;
        pr[h] = q0 * b.x * b.x + q1 * b.y * b.y + q2 * b.z * b.z + q3 * b.w * b.w;
    }
#pragma unroll
    for (int off = 16; off; off >>= 1) {
#pragma unroll
        for (int h = 0; h < 4; h++) {
            pl[h] += __shfl_xor_sync(0xffffffffu, pl[h], off);
            pr[h] += __shfl_xor_sync(0xffffffffu, pr[h], off);
        }
    }
    if (lane == 0) {
        *(float4*)(g_el2 + warp * 4) = make_float4(pl[0], pl[1], pl[2], pl[3]);
        *(float4*)(g_er2 + warp * 4) = make_float4(pr[0], pr[1], pr[2], pr[3]);
    }
}

// ---------------- CSR build ----------------
__global__ void k_hist(const int* __restrict__ dst) {
    int e = blockIdx.x * blockDim.x + threadIdx.x;
    if (e < EE) atomicAdd(&g_counts[dst[e]], 1);
}

__global__ void k_scan1() {
    __shared__ int s[1024];
    int tid = threadIdx.x;
    int t = blockIdx.x * 1024 + tid;
    int v = (t < NN) ? g_counts[t] : 0;
    s[tid] = v;
    __syncthreads();
    for (int off = 1; off < 1024; off <<= 1) {
        int x = (tid >= off) ? s[tid - off] : 0;
        __syncthreads();
        s[tid] += x;
        __syncthreads();
    }
    if (t < NN) g_offsets[t + 1] = s[tid];
    if (tid == 1023) g_chunksum[blockIdx.x] = s[1023];
}

__global__ void k_scan2(int nch) {
    if (threadIdx.x == 0 && blockIdx.x == 0) {
        int run = 0;
        for (int i = 0; i < nch; i++) { int t = g_chunksum[i]; g_chunksum[i] = run; run += t; }
    }
}

__global__ void k_scan3() {
    int tid = threadIdx.x;
    int t = blockIdx.x * 1024 + tid;
    if (t < NN) {
        int inc = g_offsets[t + 1] + g_chunksum[blockIdx.x];
        g_offsets[t + 1] = inc;
        g_cursor[t] = inc - g_counts[t];
    }
    if (t == 0) g_offsets[0] = 0;
}

__global__ void k_scatter(const int* __restrict__ src, const int* __restrict__ dst) {
    int e = blockIdx.x * blockDim.x + threadIdx.x;
    if (e < EE) {
        int d = dst[e];
        int pos = atomicAdd(&g_cursor[d], 1);
        g_csr_src[pos] = src[e];
    }
}

// ---------------- fused edge-score + online-softmax + input-space aggregation ----------------
// one warp per destination node; z[n,h,:] = sum_e a[e,h] * feat[src_e,:]
__global__ void __launch_bounds__(256)
k_agg(const float* __restrict__ feat) {
    int warp = (blockIdx.x * blockDim.x + threadIdx.x) >> 5;
    int lane = threadIdx.x & 31;
    if (warp >= NN) return;
    const int n = warp;
    const int start = g_offsets[n];
    const int end = g_offsets[n + 1];
    float* zp = g_z + n * (HH * FIN);

    if (start == end) {  // no incoming edges -> z = 0 -> out = bias (matches reference)
        float4 zz = make_float4(0.f, 0.f, 0.f, 0.f);
#pragma unroll
        for (int h = 0; h < 4; h++) *(float4*)(zp + h * FIN + lane * 4) = zz;
        return;
    }

    float4 fd = *(const float4*)(feat + n * FIN + lane * 4);
    float4 c0 = *(const float4*)(g_wc + 0 * FIN + lane * 4);
    float4 c1 = *(const float4*)(g_wc + 1 * FIN + lane * 4);
    float4 c2 = *(const float4*)(g_wc + 2 * FIN + lane * 4);
    float4 c3 = *(const float4*)(g_wc + 3 * FIN + lane * 4);
    float4 er = *(const float4*)(g_er2 + n * 4);
    // fold fd into the coefficients once: score partial = fs . (fd*wc_h)
    c0.x *= fd.x; c0.y *= fd.y; c0.z *= fd.z; c0.w *= fd.w;
    c1.x *= fd.x; c1.y *= fd.y; c1.z *= fd.z; c1.w *= fd.w;
    c2.x *= fd.x; c2.y *= fd.y; c2.z *= fd.z; c2.w *= fd.w;
    c3.x *= fd.x; c3.y *= fd.y; c3.z *= fd.z; c3.w *= fd.w;

    float m0 = -3.0e38f, m1 = -3.0e38f, m2 = -3.0e38f, m3 = -3.0e38f;
    float s0 = 0.f, s1 = 0.f, s2 = 0.f, s3 = 0.f;
    float4 z0 = make_float4(0.f, 0.f, 0.f, 0.f);
    float4 z1 = z0, z2 = z0, z3 = z0;

    for (int idx = start; idx < end; ++idx) {
        int src = __ldg(g_csr_src + idx);
        float4 fs = *(const float4*)(feat + src * FIN + lane * 4);
        float4 el = *(const float4*)(g_el2 + src * 4);

        float p0 = fs.x * c0.x + fs.y * c0.y + fs.z * c0.z + fs.w * c0.w;
        float p1 = fs.x * c1.x + fs.y * c1.y + fs.z * c1.z + fs.w * c1.w;
        float p2 = fs.x * c2.x + fs.y * c2.y + fs.z * c2.z + fs.w * c2.w;
        float p3 = fs.x * c3.x + fs.y * c3.y + fs.z * c3.z + fs.w * c3.w;
#pragma unroll
        for (int off = 16; off; off >>= 1) {
            p0 += __shfl_xor_sync(0xffffffffu, p0, off);
            p1 += __shfl_xor_sync(0xffffffffu, p1, off);
            p2 += __shfl_xor_sync(0xffffffffu, p2, off);
            p3 += __shfl_xor_sync(0xffffffffu, p3, off);
        }
        float e0 = p0 + el.x + er.x;
        float e1 = p1 + el.y + er.y;
        float e2 = p2 + el.z + er.z;
        float e3 = p3 + el.w + er.w;

        // online softmax; rescale branch is warp-uniform and rare (~log(deg) times)
        if (e0 > m0 || e1 > m1 || e2 > m2 || e3 > m3) {
            float sc0 = 1.f, sc1 = 1.f, sc2 = 1.f, sc3 = 1.f;
            if (e0 > m0) { sc0 = __expf(m0 - e0); m0 = e0; }
            if (e1 > m1) { sc1 = __expf(m1 - e1); m1 = e1; }
            if (e2 > m2) { sc2 = __expf(m2 - e2); m2 = e2; }
            if (e3 > m3) { sc3 = __expf(m3 - e3); m3 = e3; }
            s0 *= sc0; s1 *= sc1; s2 *= sc2; s3 *= sc3;
            z0.x *= sc0; z0.y *= sc0; z0.z *= sc0; z0.w *= sc0;
            z1.x *= sc1; z1.y *= sc1; z1.z *= sc1; z1.w *= sc1;
            z2.x *= sc2; z2.y *= sc2; z2.z *= sc2; z2.w *= sc2;
            z3.x *= sc3; z3.y *= sc3; z3.z *= sc3; z3.w *= sc3;
        }
        float w0 = __expf(e0 - m0);
        float w1 = __expf(e1 - m1);
        float w2 = __expf(e2 - m2);
        float w3 = __expf(e3 - m3);
        s0 += w0; s1 += w1; s2 += w2; s3 += w3;

        z0.x += w0 * fs.x; z0.y += w0 * fs.y; z0.z += w0 * fs.z; z0.w += w0 * fs.w;
        z1.x += w1 * fs.x; z1.y += w1 * fs.y; z1.z += w1 * fs.z; z1.w += w1 * fs.w;
        z2.x += w2 * fs.x; z2.y += w2 * fs.y; z2.z += w2 * fs.z; z2.w += w2 * fs.w;
        z3.x += w3 * fs.x; z3.y += w3 * fs.y; z3.z += w3 * fs.z; z3.w += w3 * fs.w;
    }

    float r0 = 1.f / s0, r1 = 1.f / s1, r2 = 1.f / s2, r3 = 1.f / s3;
    *(float4*)(zp + 0 * FIN + lane * 4) = make_float4(z0.x * r0, z0.y * r0, z0.z * r0, z0.w * r0);
    *(float4*)(zp + 1 * FIN + lane * 4) = make_float4(z1.x * r1, z1.y * r1, z1.z * r1, z1.w * r1);
    *(float4*)(zp + 2 * FIN + lane * 4) = make_float4(z2.x * r2, z2.y * r2, z2.z * r2, z2.w * r2);
    *(float4*)(zp + 3 * FIN + lane * 4) = make_float4(z3.x * r3, z3.y * r3, z3.z * r3, z3.w * r3);
}

// ---------------- post-GEMM: out[n, h*64+c] = z[n,h,:] . W[h*64+c,:] + bias ----------------
// grid (H, ceil(N/128)), block 256; tile M=128 x N=64, micro 8x4
__global__ void __launch_bounds__(256, 3)
k_gemm2(const float* __restrict__ W, const float* __restrict__ bias,
        float* __restrict__ out) {
    __shared__ float As[8][128];
    __shared__ float Bs[8][64];
    const int h = blockIdx.x;
    const int mBase = blockIdx.y * 128;
    const int tid = threadIdx.x;
    const int tr = tid >> 4, tc = tid & 15;

    float acc[8][4];
#pragma unroll
    for (int i = 0; i < 8; i++)
#pragma unroll
        for (int j = 0; j < 4; j++) acc[i][j] = 0.0f;

    const int lm = tid >> 1;
    const int lk = (tid & 1) * 4;

    for (int kk = 0; kk < FIN; kk += 8) {
        int row = mBase + lm;
        float4 av = make_float4(0.f, 0.f, 0.f, 0.f);
        if (row < NN) av = *(const float4*)(g_z + row * (HH * FIN) + h * FIN + kk + lk);
        As[lk + 0][lm] = av.x; As[lk + 1][lm] = av.y;
        As[lk + 2][lm] = av.z; As[lk + 3][lm] = av.w;
        if (tid < 128) {
            float4 bv = *(const float4*)(W + (h * FO + lm) * FIN + kk + lk);
            Bs[lk + 0][lm] = bv.x; Bs[lk + 1][lm] = bv.y;
            Bs[lk + 2][lm] = bv.z; Bs[lk + 3][lm] = bv.w;
        }
        __syncthreads();
#pragma unroll
        for (int k = 0; k < 8; k++) {
            float am[8], bn[4];
            *(float4*)(am)     = *(const float4*)(&As[k][tr * 8]);
            *(float4*)(am + 4) = *(const float4*)(&As[k][tr * 8 + 4]);
            *(float4*)(bn)     = *(const float4*)(&Bs[k][tc * 4]);
#pragma unroll
            for (int i = 0; i < 8; i++)
#pragma unroll
                for (int j = 0; j < 4; j++) acc[i][j] += am[i] * bn[j];
        }
        __syncthreads();
    }

    float4 b4 = *(const float4*)(bias + h * FO + tc * 4);
#pragma unroll
    for (int i = 0; i < 8; i++) {
        int row = mBase + tr * 8 + i;
        if (row < NN) {
            float4 o = make_float4(acc[i][0] + b4.x, acc[i][1] + b4.y,
                                   acc[i][2] + b4.z, acc[i][3] + b4.w);
            *(float4*)(out + row * NOUT + h * FO + tc * 4) = o;
        }
    }
}

// ---------------- launch ----------------
extern "C" void kernel_launch(void* const* d_in, const int* in_sizes, int n_in,
                              void* d_out, int out_size) {
    const float* feat  = (const float*)d_in[0];
    const int*   src   = (const int*)d_in[1];
    const int*   dst   = (const int*)d_in[2];
    const float* fc_w  = (const float*)d_in[3];
    const float* al    = (const float*)d_in[4];
    const float* ar    = (const float*)d_in[5];
    const float* al1   = (const float*)d_in[6];
    const float* ar1   = (const float*)d_in[7];
    const float* bias  = (const float*)d_in[8];
    float* out = (float*)d_out;

    const int nch = (NN + 1023) / 1024;  // 49

    k_prep<<<(NN + 255) / 256, 256>>>(al, ar, al1, ar1);
    k_hist<<<(EE + 255) / 256, 256>>>(dst);
    k_node<<<(NN * 32 + 255) / 256, 256>>>(feat, al1, ar1);
    k_scan1<<<nch, 1024>>>();
    k_scan2<<<1, 32>>>(nch);
    k_scan3<<<nch, 1024>>>();
    k_scatter<<<(EE + 255) / 256, 256>>>(src, dst);
    k_agg<<<(NN * 32 + 255) / 256, 256>>>(feat);
    k_gemm2<<<dim3(HH, (NN + 127) / 128), 256>>>(fc_w, bias, out);
}

// round 4
// speedup vs baseline: 1.5449x; 1.1932x over previous
#include <cuda_runtime.h>
#include <cstdint>

#define NN 50000
#define EE 800000
#define FIN 128
#define HH 4
#define FO 64
#define NOUT 256   // HH*FO

// ---- static scratch ----
__device__ float g_z[NN * HH * FIN];  // aggregated features in input space [N,4,128]
__device__ float g_el2[NN * HH];
__device__ float g_er2[NN * HH];
__device__ float g_wc[HH * FIN];
__device__ int   g_counts[NN];
__device__ int   g_offsets[NN + 1];
__device__ int   g_cursor[NN];
__device__ int   g_csr_src[EE];
__device__ int   g_chunksum[64];

// ---------------- prep: wc + zero counts ----------------
__global__ void k_prep(const float* __restrict__ al, const float* __restrict__ ar,
                       const float* __restrict__ al1, const float* __restrict__ ar1) {
    int i = blockIdx.x * blockDim.x + threadIdx.x;
    if (i < HH * FIN) g_wc[i] = al[i] * ar[i] - 2.0f * al1[i] * ar1[i];
    if (i < NN) g_counts[i] = 0;
}

// ---------------- per-node el2/er2 ----------------
__global__ void k_node(const float* __restrict__ feat,
                       const float* __restrict__ al1, const float* __restrict__ ar1) {
    int warp = (blockIdx.x * blockDim.x + threadIdx.x) >> 5;
    int lane = threadIdx.x & 31;
    if (warp >= NN) return;
    float4 f = *(const float4*)(feat + warp * FIN + lane * 4);
    float q0 = f.x * f.x, q1 = f.y * f.y, q2 = f.z * f.z, q3 = f.w * f.w;
    float pl[4], pr[4];
#pragma unroll
    for (int h = 0; h < 4; h++) {
        float4 a = *(const float4*)(al1 + h * FIN + lane * 4);
        float4 b = *(const float4*)(ar1 + h * FIN + lane * 4);
        pl[h] = q0 * a.x * a.x + q1 * a.y * a.y + q2 * a.z * a.z + q3 * a.w * a.w;
        pr[h] = q0 * b.x * b.x + q1 * b.y * b.y + q2 * b.z * b.z + q3 * b.w * b.w;
    }
#pragma unroll
    for (int off = 16; off; off >>= 1) {
#pragma unroll
        for (int h = 0; h < 4; h++) {
            pl[h] += __shfl_xor_sync(0xffffffffu, pl[h], off);
            pr[h] += __shfl_xor_sync(0xffffffffu, pr[h], off);
        }
    }
    if (lane == 0) {
        *(float4*)(g_el2 + warp * 4) = make_float4(pl[0], pl[1], pl[2], pl[3]);
        *(float4*)(g_er2 + warp * 4) = make_float4(pr[0], pr[1], pr[2], pr[3]);
    }
}

// ---------------- CSR build ----------------
__global__ void k_hist(const int* __restrict__ dst) {
    int e = blockIdx.x * blockDim.x + threadIdx.x;
    if (e < EE) atomicAdd(&g_counts[dst[e]], 1);
}
__global__ void k_scan1() {
    __shared__ int s[1024];
    int tid = threadIdx.x;
    int t = blockIdx.x * 1024 + tid;
    int v = (t < NN) ? g_counts[t] : 0;
    s[tid] = v;
    __syncthreads();
    for (int off = 1; off < 1024; off <<= 1) {
        int x = (tid >= off) ? s[tid - off] : 0;
        __syncthreads();
        s[tid] += x;
        __syncthreads();
    }
    if (t < NN) g_offsets[t + 1] = s[tid];
    if (tid == 1023) g_chunksum[blockIdx.x] = s[1023];
}
__global__ void k_scan2(int nch) {
    if (threadIdx.x == 0 && blockIdx.x == 0) {
        int run = 0;
        for (int i = 0; i < nch; i++) { int t = g_chunksum[i]; g_chunksum[i] = run; run += t; }
    }
}
__global__ void k_scan3() {
    int tid = threadIdx.x;
    int t = blockIdx.x * 1024 + tid;
    if (t < NN) {
        int inc = g_offsets[t + 1] + g_chunksum[blockIdx.x];
        g_offsets[t + 1] = inc;
        g_cursor[t] = inc - g_counts[t];
    }
    if (t == 0) g_offsets[0] = 0;
}
__global__ void k_scatter(const int* __restrict__ src, const int* __restrict__ dst) {
    int e = blockIdx.x * blockDim.x + threadIdx.x;
    if (e < EE) {
        int d = dst[e];
        int pos = atomicAdd(&g_cursor[d], 1);
        g_csr_src[pos] = src[e];
    }
}

// ---------------- fused score + online-softmax + input-space agg ----------------
// one warp per destination node. Score reduction: fold 4 head partials so head
// (lane&3) lives on each lane-class, then 6 shfl total; single exp per lane.
__global__ void __launch_bounds__(256)
k_agg(const float* __restrict__ feat) {
    int warp = (blockIdx.x * blockDim.x + threadIdx.x) >> 5;
    int lane = threadIdx.x & 31;
    if (warp >= NN) return;
    const int n = warp;
    const int start = g_offsets[n];
    const int end = g_offsets[n + 1];
    const int hsel = lane & 3;
    float* zp = g_z + (size_t)n * (HH * FIN);

    if (start == end) {  // z = 0 -> out = bias
        float4 zz = make_float4(0.f, 0.f, 0.f, 0.f);
#pragma unroll
        for (int h = 0; h < 4; h++) *(float4*)(zp + h * FIN + lane * 4) = zz;
        return;
    }

    float4 fd = *(const float4*)(feat + n * FIN + lane * 4);
    float4 c0 = *(const float4*)(g_wc + 0 * FIN + lane * 4);
    float4 c1 = *(const float4*)(g_wc + 1 * FIN + lane * 4);
    float4 c2 = *(const float4*)(g_wc + 2 * FIN + lane * 4);
    float4 c3 = *(const float4*)(g_wc + 3 * FIN + lane * 4);
    c0.x *= fd.x; c0.y *= fd.y; c0.z *= fd.z; c0.w *= fd.w;
    c1.x *= fd.x; c1.y *= fd.y; c1.z *= fd.z; c1.w *= fd.w;
    c2.x *= fd.x; c2.y *= fd.y; c2.z *= fd.z; c2.w *= fd.w;
    c3.x *= fd.x; c3.y *= fd.y; c3.z *= fd.z; c3.w *= fd.w;
    float er_s = __ldg(g_er2 + n * 4 + hsel);

    float m = -3.0e38f, s = 0.f;
    float4 z0 = make_float4(0.f, 0.f, 0.f, 0.f);
    float4 z1 = z0, z2 = z0, z3 = z0;

    for (int idx = start; idx < end; ++idx) {
        int src = __ldg(g_csr_src + idx);
        float4 fs = *(const float4*)(feat + src * FIN + lane * 4);
        float el_s = __ldg(g_el2 + src * 4 + hsel);

        float p0 = fs.x * c0.x + fs.y * c0.y + fs.z * c0.z + fs.w * c0.w;
        float p1 = fs.x * c1.x + fs.y * c1.y + fs.z * c1.z + fs.w * c1.w;
        float p2 = fs.x * c2.x + fs.y * c2.y + fs.z * c2.z + fs.w * c2.w;
        float p3 = fs.x * c3.x + fs.y * c3.y + fs.z * c3.z + fs.w * c3.w;

        // pairwise fold: after this, lane-class lane&3 holds head lane&3 partial
        float u01 = (lane & 1) ? p1 : p0;
        float t01 = (lane & 1) ? p0 : p1;
        u01 += __shfl_xor_sync(0xffffffffu, t01, 1);
        float u23 = (lane & 1) ? p3 : p2;
        float t23 = (lane & 1) ? p2 : p3;
        u23 += __shfl_xor_sync(0xffffffffu, t23, 1);
        float v = (lane & 2) ? u23 : u01;
        float t = (lane & 2) ? u01 : u23;
        v += __shfl_xor_sync(0xffffffffu, t, 2);
        v += __shfl_xor_sync(0xffffffffu, v, 4);
        v += __shfl_xor_sync(0xffffffffu, v, 8);
        v += __shfl_xor_sync(0xffffffffu, v, 16);

        float e = v + el_s + er_s;   // head = lane&3, replicated x8

        float sc = 1.f;
        if (e > m) { sc = __expf(m - e); m = e; }
        float w = __expf(e - m);
        s = s * sc + w;

        float w0 = __shfl_sync(0xffffffffu, w, 0);
        float w1 = __shfl_sync(0xffffffffu, w, 1);
        float w2 = __shfl_sync(0xffffffffu, w, 2);
        float w3 = __shfl_sync(0xffffffffu, w, 3);

        if (__any_sync(0xffffffffu, sc != 1.0f)) {
            float s0 = __shfl_sync(0xffffffffu, sc, 0);
            float s1 = __shfl_sync(0xffffffffu, sc, 1);
            float s2 = __shfl_sync(0xffffffffu, sc, 2);
            float s3 = __shfl_sync(0xffffffffu, sc, 3);
            z0.x *= s0; z0.y *= s0; z0.z *= s0; z0.w *= s0;
            z1.x *= s1; z1.y *= s1; z1.z *= s1; z1.w *= s1;
            z2.x *= s2; z2.y *= s2; z2.z *= s2; z2.w *= s2;
            z3.x *= s3; z3.y *= s3; z3.z *= s3; z3.w *= s3;
        }
        z0.x += w0 * fs.x; z0.y += w0 * fs.y; z0.z += w0 * fs.z; z0.w += w0 * fs.w;
        z1.x += w1 * fs.x; z1.y += w1 * fs.y; z1.z += w1 * fs.z; z1.w += w1 * fs.w;
        z2.x += w2 * fs.x; z2.y += w2 * fs.y; z2.z += w2 * fs.z; z2.w += w2 * fs.w;
        z3.x += w3 * fs.x; z3.y += w3 * fs.y; z3.z += w3 * fs.z; z3.w += w3 * fs.w;
    }

    float rinv = 1.f / s;
    float r0 = __shfl_sync(0xffffffffu, rinv, 0);
    float r1 = __shfl_sync(0xffffffffu, rinv, 1);
    float r2 = __shfl_sync(0xffffffffu, rinv, 2);
    float r3 = __shfl_sync(0xffffffffu, rinv, 3);

    *(float4*)(zp + 0 * FIN + lane * 4) = make_float4(z0.x * r0, z0.y * r0, z0.z * r0, z0.w * r0);
    *(float4*)(zp + 1 * FIN + lane * 4) = make_float4(z1.x * r1, z1.y * r1, z1.z * r1, z1.w * r1);
    *(float4*)(zp + 2 * FIN + lane * 4) = make_float4(z2.x * r2, z2.y * r2, z2.z * r2, z2.w * r2);
    *(float4*)(zp + 3 * FIN + lane * 4) = make_float4(z3.x * r3, z3.y * r3, z3.z * r3, z3.w * r3);
}

// ---------------- post-GEMM: out[n, h*64+c] = z[n,h,:] . W[h*64+c,:] + bias ----------------
__global__ void __launch_bounds__(256, 3)
k_gemm2(const float* __restrict__ W, const float* __restrict__ bias,
        float* __restrict__ out) {
    __shared__ float As[8][128];
    __shared__ float Bs[8][64];
    const int h = blockIdx.x;
    const int mBase = blockIdx.y * 128;
    const int tid = threadIdx.x;
    const int tr = tid >> 4, tc = tid & 15;

    float acc[8][4];
#pragma unroll
    for (int i = 0; i < 8; i++)
#pragma unroll
        for (int j = 0; j < 4; j++) acc[i][j] = 0.0f;

    const int lm = tid >> 1;
    const int lk = (tid & 1) * 4;

    for (int kk = 0; kk < FIN; kk += 8) {
        int row = mBase + lm;
        float4 av = make_float4(0.f, 0.f, 0.f, 0.f);
        if (row < NN) av = *(const float4*)(g_z + (size_t)row * (HH * FIN) + h * FIN + kk + lk);
        As[lk + 0][lm] = av.x; As[lk + 1][lm] = av.y;
        As[lk + 2][lm] = av.z; As[lk + 3][lm] = av.w;
        if (tid < 128) {
            float4 bv = *(const float4*)(W + (h * FO + lm) * FIN + kk + lk);
            Bs[lk + 0][lm] = bv.x; Bs[lk + 1][lm] = bv.y;
            Bs[lk + 2][lm] = bv.z; Bs[lk + 3][lm] = bv.w;
        }
        __syncthreads();
#pragma unroll
        for (int k = 0; k < 8; k++) {
            float am[8], bn[4];
            *(float4*)(am)     = *(const float4*)(&As[k][tr * 8]);
            *(float4*)(am + 4) = *(const float4*)(&As[k][tr * 8 + 4]);
            *(float4*)(bn)     = *(const float4*)(&Bs[k][tc * 4]);
#pragma unroll
            for (int i = 0; i < 8; i++)
#pragma unroll
                for (int j = 0; j < 4; j++) acc[i][j] += am[i] * bn[j];
        }
        __syncthreads();
    }

    float4 b4 = *(const float4*)(bias + h * FO + tc * 4);
#pragma unroll
    for (int i = 0; i < 8; i++) {
        int row = mBase + tr * 8 + i;
        if (row < NN) {
            float4 o = make_float4(acc[i][0] + b4.x, acc[i][1] + b4.y,
                                   acc[i][2] + b4.z, acc[i][3] + b4.w);
            *(float4*)(out + (size_t)row * NOUT + h * FO + tc * 4) = o;
        }
    }
}

// ---------------- launch ----------------
extern "C" void kernel_launch(void* const* d_in, const int* in_sizes, int n_in,
                              void* d_out, int out_size) {
    const float* feat  = (const float*)d_in[0];
    const int*   src   = (const int*)d_in[1];
    const int*   dst   = (const int*)d_in[2];
    const float* fc_w  = (const float*)d_in[3];
    const float* al    = (const float*)d_in[4];
    const float* ar    = (const float*)d_in[5];
    const float* al1   = (const float*)d_in[6];
    const float* ar1   = (const float*)d_in[7];
    const float* bias  = (const float*)d_in[8];
    float* out = (float*)d_out;

    const int nch = (NN + 1023) / 1024;  // 49

    k_prep<<<(NN + 255) / 256, 256>>>(al, ar, al1, ar1);
    k_hist<<<(EE + 255) / 256, 256>>>(dst);
    k_node<<<(NN * 32 + 255) / 256, 256>>>(feat, al1, ar1);
    k_scan1<<<nch, 1024>>>();
    k_scan2<<<1, 32>>>(nch);
    k_scan3<<<nch, 1024>>>();
    k_scatter<<<(EE + 255) / 256, 256>>>(src, dst);
    k_agg<<<(NN * 32 + 255) / 256, 256>>>(feat);
    k_gemm2<<<dim3(HH, (NN + 127) / 128), 256>>>(fc_w, bias, out);
}

// round 5
// speedup vs baseline: 1.5531x; 1.0053x over previous
#include <cuda_runtime.h>
#include <cstdint>

#define NN 50000
#define EE 800000
#define FIN 128
#define HH 4
#define FO 64
#define NOUT 256   // HH*FO

// ---- static scratch ----
__device__ float g_z[NN * HH * FIN];  // aggregated features in input space [N,4,128]
__device__ float g_el2[NN * HH];
__device__ float g_er2[NN * HH];
__device__ float g_wc[HH * FIN];
__device__ int   g_counts[NN];
__device__ int   g_offsets[NN + 1];
__device__ int   g_cursor[NN];
__device__ int   g_csr_src[EE];
__device__ int   g_chunksum[64];

// ---- packed f32x2 helpers (PTX ISA 8.6, sm_100+) ----
typedef unsigned long long u64t;
__device__ __forceinline__ u64t pack2(float lo, float hi) {
    u64t r;
    asm("mov.b64 %0, {%1, %2};" : "=l"(r) : "f"(lo), "f"(hi));
    return r;
}
__device__ __forceinline__ void unpack2(u64t v, float& lo, float& hi) {
    asm("mov.b64 {%0, %1}, %2;" : "=f"(lo), "=f"(hi) : "l"(v));
}
__device__ __forceinline__ void ffma2(u64t& d, u64t a, u64t b) {
    asm("fma.rn.f32x2 %0, %1, %2, %0;" : "+l"(d) : "l"(a), "l"(b));
}
__device__ __forceinline__ u64t fmul2(u64t a, u64t b) {
    u64t r;
    asm("mul.rn.f32x2 %0, %1, %2;" : "=l"(r) : "l"(a), "l"(b));
    return r;
}

// ---------------- prep: wc + zero counts ----------------
__global__ void k_prep(const float* __restrict__ al, const float* __restrict__ ar,
                       const float* __restrict__ al1, const float* __restrict__ ar1) {
    int i = blockIdx.x * blockDim.x + threadIdx.x;
    if (i < HH * FIN) g_wc[i] = al[i] * ar[i] - 2.0f * al1[i] * ar1[i];
    if (i < NN) g_counts[i] = 0;
}

// ---------------- per-node el2/er2 ----------------
__global__ void k_node(const float* __restrict__ feat,
                       const float* __restrict__ al1, const float* __restrict__ ar1) {
    int warp = (blockIdx.x * blockDim.x + threadIdx.x) >> 5;
    int lane = threadIdx.x & 31;
    if (warp >= NN) return;
    float4 f = *(const float4*)(feat + warp * FIN + lane * 4);
    float q0 = f.x * f.x, q1 = f.y * f.y, q2 = f.z * f.z, q3 = f.w * f.w;
    float pl[4], pr[4];
#pragma unroll
    for (int h = 0; h < 4; h++) {
        float4 a = *(const float4*)(al1 + h * FIN + lane * 4);
        float4 b = *(const float4*)(ar1 + h * FIN + lane * 4);
        pl[h] = q0 * a.x * a.x + q1 * a.y * a.y + q2 * a.z * a.z + q3 * a.w * a.w;
        pr[h] = q0 * b.x * b.x + q1 * b.y * b.y + q2 * b.z * b.z + q3 * b.w * b.w;
    }
#pragma unroll
    for (int off = 16; off; off >>= 1) {
#pragma unroll
        for (int h = 0; h < 4; h++) {
            pl[h] += __shfl_xor_sync(0xffffffffu, pl[h], off);
            pr[h] += __shfl_xor_sync(0xffffffffu, pr[h], off);
        }
    }
    if (lane == 0) {
        *(float4*)(g_el2 + warp * 4) = make_float4(pl[0], pl[1], pl[2], pl[3]);
        *(float4*)(g_er2 + warp * 4) = make_float4(pr[0], pr[1], pr[2], pr[3]);
    }
}

// ---------------- CSR build ----------------
__global__ void k_hist(const int* __restrict__ dst) {
    int e4 = (blockIdx.x * blockDim.x + threadIdx.x) * 4;
    if (e4 < EE) {   // EE % 4 == 0
        int4 d4 = *(const int4*)(dst + e4);
        atomicAdd(&g_counts[d4.x], 1);
        atomicAdd(&g_counts[d4.y], 1);
        atomicAdd(&g_counts[d4.z], 1);
        atomicAdd(&g_counts[d4.w], 1);
    }
}

__global__ void k_scan1() {
    __shared__ int wsum[32];
    int tid = threadIdx.x;                    // 1024
    int t = blockIdx.x * 1024 + tid;
    int lane = tid & 31, wid = tid >> 5;
    int x = (t < NN) ? g_counts[t] : 0;
#pragma unroll
    for (int off = 1; off < 32; off <<= 1) {
        int y = __shfl_up_sync(0xffffffffu, x, off);
        if (lane >= off) x += y;
    }
    if (lane == 31) wsum[wid] = x;
    __syncthreads();
    if (wid == 0) {
        int ws = wsum[lane];
#pragma unroll
        for (int off = 1; off < 32; off <<= 1) {
            int y = __shfl_up_sync(0xffffffffu, ws, off);
            if (lane >= off) ws += y;
        }
        wsum[lane] = ws;
    }
    __syncthreads();
    if (wid > 0) x += wsum[wid - 1];
    if (t < NN) g_offsets[t + 1] = x;
    if (tid == 1023) g_chunksum[blockIdx.x] = x;
}
__global__ void k_scan2(int nch) {
    if (threadIdx.x == 0 && blockIdx.x == 0) {
        int run = 0;
        for (int i = 0; i < nch; i++) { int t = g_chunksum[i]; g_chunksum[i] = run; run += t; }
    }
}
__global__ void k_scan3() {
    int tid = threadIdx.x;
    int t = blockIdx.x * 1024 + tid;
    if (t < NN) {
        int inc = g_offsets[t + 1] + g_chunksum[blockIdx.x];
        g_offsets[t + 1] = inc;
        g_cursor[t] = inc - g_counts[t];
    }
    if (t == 0) g_offsets[0] = 0;
}
__global__ void k_scatter(const int* __restrict__ src, const int* __restrict__ dst) {
    int e4 = (blockIdx.x * blockDim.x + threadIdx.x) * 4;
    if (e4 < EE) {
        int4 s4 = *(const int4*)(src + e4);
        int4 d4 = *(const int4*)(dst + e4);
        int p0 = atomicAdd(&g_cursor[d4.x], 1); g_csr_src[p0] = s4.x;
        int p1 = atomicAdd(&g_cursor[d4.y], 1); g_csr_src[p1] = s4.y;
        int p2 = atomicAdd(&g_cursor[d4.z], 1); g_csr_src[p2] = s4.z;
        int p3 = atomicAdd(&g_cursor[d4.w], 1); g_csr_src[p3] = s4.w;
    }
}

// ---------------- fused score + online-softmax + input-space agg ----------------
__global__ void __launch_bounds__(256)
k_agg(const float* __restrict__ feat) {
    int warp = (blockIdx.x * blockDim.x + threadIdx.x) >> 5;
    int lane = threadIdx.x & 31;
    if (warp >= NN) return;
    const int n = warp;
    const int start = g_offsets[n];
    const int end = g_offsets[n + 1];
    const int hsel = lane & 3;
    float* zp = g_z + (size_t)n * (HH * FIN);

    if (start == end) {  // z = 0 -> out = bias
        float4 zz = make_float4(0.f, 0.f, 0.f, 0.f);
#pragma unroll
        for (int h = 0; h < 4; h++) *(float4*)(zp + h * FIN + lane * 4) = zz;
        return;
    }

    float4 fd = *(const float4*)(feat + n * FIN + lane * 4);
    float4 c0 = *(const float4*)(g_wc + 0 * FIN + lane * 4);
    float4 c1 = *(const float4*)(g_wc + 1 * FIN + lane * 4);
    float4 c2 = *(const float4*)(g_wc + 2 * FIN + lane * 4);
    float4 c3 = *(const float4*)(g_wc + 3 * FIN + lane * 4);
    c0.x *= fd.x; c0.y *= fd.y; c0.z *= fd.z; c0.w *= fd.w;
    c1.x *= fd.x; c1.y *= fd.y; c1.z *= fd.z; c1.w *= fd.w;
    c2.x *= fd.x; c2.y *= fd.y; c2.z *= fd.z; c2.w *= fd.w;
    c3.x *= fd.x; c3.y *= fd.y; c3.z *= fd.z; c3.w *= fd.w;
    float er_s = __ldg(g_er2 + n * 4 + hsel);

    float m = -3.0e38f, s = 0.f;
    u64t z0a = 0, z0b = 0, z1a = 0, z1b = 0;   // 0.0f|0.0f bit pattern
    u64t z2a = 0, z2b = 0, z3a = 0, z3b = 0;

    for (int idx = start; idx < end; ++idx) {
        int src = __ldg(g_csr_src + idx);
        float4 fs = *(const float4*)(feat + src * FIN + lane * 4);
        float el_s = __ldg(g_el2 + src * 4 + hsel);

        float p0 = fs.x * c0.x + fs.y * c0.y + fs.z * c0.z + fs.w * c0.w;
        float p1 = fs.x * c1.x + fs.y * c1.y + fs.z * c1.z + fs.w * c1.w;
        float p2 = fs.x * c2.x + fs.y * c2.y + fs.z * c2.z + fs.w * c2.w;
        float p3 = fs.x * c3.x + fs.y * c3.y + fs.z * c3.z + fs.w * c3.w;

        // fold 4 head partials to lane-class lane&3, then butterfly: 6 shfl total
        float u01 = (lane & 1) ? p1 : p0;
        float t01 = (lane & 1) ? p0 : p1;
        u01 += __shfl_xor_sync(0xffffffffu, t01, 1);
        float u23 = (lane & 1) ? p3 : p2;
        float t23 = (lane & 1) ? p2 : p3;
        u23 += __shfl_xor_sync(0xffffffffu, t23, 1);
        float v = (lane & 2) ? u23 : u01;
        float t = (lane & 2) ? u01 : u23;
        v += __shfl_xor_sync(0xffffffffu, t, 2);
        v += __shfl_xor_sync(0xffffffffu, v, 4);
        v += __shfl_xor_sync(0xffffffffu, v, 8);
        v += __shfl_xor_sync(0xffffffffu, v, 16);

        float e = v + el_s + er_s;   // head = lane&3, replicated x8

        float sc = 1.f;
        if (e > m) { sc = __expf(m - e); m = e; }
        float w = __expf(e - m);
        s = s * sc + w;

        float w0 = __shfl_sync(0xffffffffu, w, 0);
        float w1 = __shfl_sync(0xffffffffu, w, 1);
        float w2 = __shfl_sync(0xffffffffu, w, 2);
        float w3 = __shfl_sync(0xffffffffu, w, 3);

        if (__any_sync(0xffffffffu, sc != 1.0f)) {
            float s0 = __shfl_sync(0xffffffffu, sc, 0);
            float s1 = __shfl_sync(0xffffffffu, sc, 1);
            float s2 = __shfl_sync(0xffffffffu, sc, 2);
            float s3 = __shfl_sync(0xffffffffu, sc, 3);
            u64t sd0 = pack2(s0, s0), sd1 = pack2(s1, s1);
            u64t sd2 = pack2(s2, s2), sd3 = pack2(s3, s3);
            z0a = fmul2(z0a, sd0); z0b = fmul2(z0b, sd0);
            z1a = fmul2(z1a, sd1); z1b = fmul2(z1b, sd1);
            z2a = fmul2(z2a, sd2); z2b = fmul2(z2b, sd2);
            z3a = fmul2(z3a, sd3); z3b = fmul2(z3b, sd3);
        }
        u64t fsa = pack2(fs.x, fs.y), fsb = pack2(fs.z, fs.w);
        u64t wd0 = pack2(w0, w0), wd1 = pack2(w1, w1);
        u64t wd2 = pack2(w2, w2), wd3 = pack2(w3, w3);
        ffma2(z0a, wd0, fsa); ffma2(z0b, wd0, fsb);
        ffma2(z1a, wd1, fsa); ffma2(z1b, wd1, fsb);
        ffma2(z2a, wd2, fsa); ffma2(z2b, wd2, fsb);
        ffma2(z3a, wd3, fsa); ffma2(z3b, wd3, fsb);
    }

    float rinv = 1.f / s;
    float r0 = __shfl_sync(0xffffffffu, rinv, 0);
    float r1 = __shfl_sync(0xffffffffu, rinv, 1);
    float r2 = __shfl_sync(0xffffffffu, rinv, 2);
    float r3 = __shfl_sync(0xffffffffu, rinv, 3);

    float4 o;
    unpack2(z0a, o.x, o.y); unpack2(z0b, o.z, o.w);
    *(float4*)(zp + 0 * FIN + lane * 4) = make_float4(o.x * r0, o.y * r0, o.z * r0, o.w * r0);
    unpack2(z1a, o.x, o.y); unpack2(z1b, o.z, o.w);
    *(float4*)(zp + 1 * FIN + lane * 4) = make_float4(o.x * r1, o.y * r1, o.z * r1, o.w * r1);
    unpack2(z2a, o.x, o.y); unpack2(z2b, o.z, o.w);
    *(float4*)(zp + 2 * FIN + lane * 4) = make_float4(o.x * r2, o.y * r2, o.z * r2, o.w * r2);
    unpack2(z3a, o.x, o.y); unpack2(z3b, o.z, o.w);
    *(float4*)(zp + 3 * FIN + lane * 4) = make_float4(o.x * r3, o.y * r3, o.z * r3, o.w * r3);
}

// ---------------- post-GEMM with FFMA2: out[n, h*64+c] = z[n,h,:] . W[h*64+c,:] + bias ----------------
// grid (H, ceil(N/128)), block 256; tile M=128 x N=64; micro: 8 rows (4 pairs) x 4 cols
__global__ void __launch_bounds__(256, 3)
k_gemm2(const float* __restrict__ W, const float* __restrict__ bias,
        float* __restrict__ out) {
    __shared__ float As[8][128];
    __shared__ float Bs[8][64];
    const int h = blockIdx.x;
    const int mBase = blockIdx.y * 128;
    const int tid = threadIdx.x;
    const int tr = tid >> 4, tc = tid & 15;

    u64t acc2[4][4];   // [row-pair][col] ; each holds (row 2*i2, row 2*i2+1)
#pragma unroll
    for (int i = 0; i < 4; i++)
#pragma unroll
        for (int j = 0; j < 4; j++) acc2[i][j] = 0ull;

    const int lm = tid >> 1;
    const int lk = (tid & 1) * 4;

    for (int kk = 0; kk < FIN; kk += 8) {
        int row = mBase + lm;
        float4 av = make_float4(0.f, 0.f, 0.f, 0.f);
        if (row < NN) av = *(const float4*)(g_z + (size_t)row * (HH * FIN) + h * FIN + kk + lk);
        As[lk + 0][lm] = av.x; As[lk + 1][lm] = av.y;
        As[lk + 2][lm] = av.z; As[lk + 3][lm] = av.w;
        if (tid < 128) {
            float4 bv = *(const float4*)(W + (h * FO + lm) * FIN + kk + lk);
            Bs[lk + 0][lm] = bv.x; Bs[lk + 1][lm] = bv.y;
            Bs[lk + 2][lm] = bv.z; Bs[lk + 3][lm] = bv.w;
        }
        __syncthreads();
#pragma unroll
        for (int k = 0; k < 8; k++) {
            u64t am2[4];
#pragma unroll
            for (int i = 0; i < 4; i++)
                am2[i] = *(const u64t*)(&As[k][tr * 8 + i * 2]);   // 8B-aligned pair
            float4 b4 = *(const float4*)(&Bs[k][tc * 4]);
            u64t bd0 = pack2(b4.x, b4.x), bd1 = pack2(b4.y, b4.y);
            u64t bd2 = pack2(b4.z, b4.z), bd3 = pack2(b4.w, b4.w);
#pragma unroll
            for (int i = 0; i < 4; i++) {
                ffma2(acc2[i][0], am2[i], bd0);
                ffma2(acc2[i][1], am2[i], bd1);
                ffma2(acc2[i][2], am2[i], bd2);
                ffma2(acc2[i][3], am2[i], bd3);
            }
        }
        __syncthreads();
    }

    float4 b4 = *(const float4*)(bias + h * FO + tc * 4);
#pragma unroll
    for (int i = 0; i < 4; i++) {
        int r0 = mBase + tr * 8 + i * 2;
        float lo0, hi0, lo1, hi1, lo2, hi2, lo3, hi3;
        unpack2(acc2[i][0], lo0, hi0);
        unpack2(acc2[i][1], lo1, hi1);
        unpack2(acc2[i][2], lo2, hi2);
        unpack2(acc2[i][3], lo3, hi3);
        if (r0 < NN) {
            *(float4*)(out + (size_t)r0 * NOUT + h * FO + tc * 4) =
                make_float4(lo0 + b4.x, lo1 + b4.y, lo2 + b4.z, lo3 + b4.w);
        }
        if (r0 + 1 < NN) {
            *(float4*)(out + (size_t)(r0 + 1) * NOUT + h * FO + tc * 4) =
                make_float4(hi0 + b4.x, hi1 + b4.y, hi2 + b4.z, hi3 + b4.w);
        }
    }
}

// ---------------- launch ----------------
extern "C" void kernel_launch(void* const* d_in, const int* in_sizes, int n_in,
                              void* d_out, int out_size) {
    const float* feat  = (const float*)d_in[0];
    const int*   src   = (const int*)d_in[1];
    const int*   dst   = (const int*)d_in[2];
    const float* fc_w  = (const float*)d_in[3];
    const float* al    = (const float*)d_in[4];
    const float* ar    = (const float*)d_in[5];
    const float* al1   = (const float*)d_in[6];
    const float* ar1   = (const float*)d_in[7];
    const float* bias  = (const float*)d_in[8];
    float* out = (float*)d_out;

    const int nch = (NN + 1023) / 1024;  // 49

    k_prep<<<(NN + 255) / 256, 256>>>(al, ar, al1, ar1);
    k_hist<<<(EE / 4 + 255) / 256, 256>>>(dst);
    k_node<<<(NN * 32 + 255) / 256, 256>>>(feat, al1, ar1);
    k_scan1<<<nch, 1024>>>();
    k_scan2<<<1, 32>>>(nch);
    k_scan3<<<nch, 1024>>>();
    k_scatter<<<(EE / 4 + 255) / 256, 256>>>(src, dst);
    k_agg<<<(NN * 32 + 255) / 256, 256>>>(feat);
    k_gemm2<<<dim3(HH, (NN + 127) / 128), 256>>>(fc_w, bias, out);
}